// round 17
// baseline (speedup 1.0000x reference)
#include <cuda_runtime.h>
#include <cuda_fp16.h>

// Problem: B=4, D=64, K=32, N=8192. Total floats = 2,097,152 = 524288 float4.
#define Kk 32
#define Dk 64
#define GRIDA 512            // encode: TPB 256, 4 float4/thread; blk = bd*2 + c2
#define GRIDC 512            // scale:  TPB 128, 8 float4/thread; blk = bd*2 + c2

typedef unsigned int u32;

// Partials in [b][chunk(2)][d(64)] layout -> warp-coalesced gamma reads.
__device__ float g_partial[512];

// ---- fp16x2 helpers (carried in u32) ----
__device__ __forceinline__ u32 cvt2h(float hi, float lo) {   // {lo, hi}
    u32 r; asm("cvt.rn.f16x2.f32 %0, %1, %2;" : "=r"(r) : "f"(hi), "f"(lo)); return r;
}
__device__ __forceinline__ u32 hex2(u32 a) {                 // 2 exps, 1 MUFU op
    u32 r; asm("ex2.approx.f16x2 %0, %1;" : "=r"(r) : "r"(a)); return r;
}
__device__ __forceinline__ u32 hadd2(u32 a, u32 b) {
    u32 r; asm("add.rn.f16x2 %0, %1, %2;" : "=r"(r) : "r"(a), "r"(b)); return r;
}
__device__ __forceinline__ u32 hmul2(u32 a, u32 b) {
    u32 r; asm("mul.rn.f16x2 %0, %1, %2;" : "=r"(r) : "r"(a), "r"(b)); return r;
}
__device__ __forceinline__ u32 hfma2(u32 a, u32 b, u32 c) {
    u32 r; asm("fma.rn.f16x2 %0, %1, %2, %3;" : "=r"(r) : "r"(a), "r"(b), "r"(c)); return r;
}
__device__ __forceinline__ float lo2f(u32 h) {
    float f; asm("{.reg .f16 l,h; mov.b32 {l,h}, %1; cvt.f32.f16 %0, l;}" : "=f"(f) : "r"(h)); return f;
}
__device__ __forceinline__ float hi2f(u32 h) {
    float f; asm("{.reg .f16 l,h; mov.b32 {l,h}, %1; cvt.f32.f16 %0, h;}" : "=f"(f) : "r"(h)); return f;
}

// ---- Kernel A: E (unscaled) + partials; all-half loop, 4 float4/thread ----
// e_k = exp2(hsl*x^2 + hp1*x + hp0);  E = x + (sum e*(-c)) / (sum e)
__global__ void __launch_bounds__(256)
k_encode(const float* __restrict__ X, const float* __restrict__ cw,
         const float* __restrict__ sc, float* __restrict__ out)
{
    __shared__ uint4 s_c[Kk];    // (hp1, hp0, hsl, hc) as half2 each
    __shared__ float s_red[8];

    const int t   = threadIdx.x;
    const int blk = blockIdx.x;
    const int d   = (blk >> 1) & 63;    // blk = (b*64+d)*2 + c2
    const int b   = blk >> 7;
    const int c2  = blk & 1;

    if (t < Kk) {
        const float c   = cw[t * Dk + d];
        const float slx = sc[t * Dk + d] * 1.4426950408889634f;  // fold log2(e)
        const float p1  = -2.0f * c * slx;
        const float p0  = c * c * slx;
        s_c[t] = make_uint4(cvt2h(p1, p1), cvt2h(p0, p0),
                            cvt2h(slx, slx), cvt2h(-c, -c));
    }
    __syncthreads();

    float4 v[4];
    #pragma unroll
    for (int i = 0; i < 4; i++) v[i] = ((const float4*)X)[blk * 1024 + i * 256 + t];

    u32 hx[8], hq[8], dn[8], w[8];
    #pragma unroll
    for (int i = 0; i < 4; i++) {
        hx[i * 2 + 0] = cvt2h(v[i].y, v[i].x);
        hx[i * 2 + 1] = cvt2h(v[i].w, v[i].z);
    }
    #pragma unroll
    for (int p = 0; p < 8; p++) {
        hq[p] = hmul2(hx[p], hx[p]);
        dn[p] = 0u;  w[p] = 0u;
    }

    #pragma unroll 4
    for (int k = 0; k < Kk; k++) {
        const uint4 cc = s_c[k];                 // ONE LDS.128 per k (16 elems)
        const u32 hp1 = cc.x, hp0 = cc.y, hsl = cc.z, hc = cc.w;
        #pragma unroll
        for (int p = 0; p < 8; p++) {
            const u32 a = hfma2(hsl, hq[p], hfma2(hp1, hx[p], hp0));  // arg <= 0
            const u32 e = hex2(a);               // 2 exps per MUFU op
            dn[p] = hadd2(dn[p], e);
            w[p]  = hfma2(e, hc, w[p]);          // w = sum e*(-c)
        }
    }

    float ssum = 0.f;
    #pragma unroll
    for (int i = 0; i < 4; i++) {
        float4 o;                                // E = x + w/den (fp32 finish)
        o.x = v[i].x + __fdividef(lo2f(w[i*2]),   lo2f(dn[i*2]));
        o.y = v[i].y + __fdividef(hi2f(w[i*2]),   hi2f(dn[i*2]));
        o.z = v[i].z + __fdividef(lo2f(w[i*2+1]), lo2f(dn[i*2+1]));
        o.w = v[i].w + __fdividef(hi2f(w[i*2+1]), hi2f(dn[i*2+1]));
        ((float4*)out)[blk * 1024 + i * 256 + t] = o;   // unscaled E
        ssum += ((o.x + o.y) + (o.z + o.w));
    }

    #pragma unroll
    for (int off = 16; off > 0; off >>= 1)
        ssum += __shfl_xor_sync(0xffffffffu, ssum, off);
    if ((t & 31) == 0) s_red[t >> 5] = ssum;
    __syncthreads();
    if (t == 0) {
        float s = 0.f;
        #pragma unroll
        for (int wv = 0; wv < 8; wv++) s += s_red[wv];
        g_partial[b * 128 + c2 * 64 + d] = s;    // [b][chunk][d] layout
    }
}

// ---- Kernel B: warp-autonomous scale; TPB 128, 8 float4/thread ----
__global__ void __launch_bounds__(128)
k_scale(const float* __restrict__ fw, const float* __restrict__ fb,
        float* __restrict__ out)
{
    const int t    = threadIdx.x;
    const int lane = t & 31;
    const int blk  = blockIdx.x;
    const int d    = (blk >> 1) & 63;   // blk = (b*64+d)*2 + c2
    const int b    = blk >> 7;

    // Issue ALL 8 E loads first; they overlap the gamma chain below.
    float4* base = (float4*)out + blk * 1024;
    float4 e[8];
    #pragma unroll
    for (int i = 0; i < 8; i++) e[i] = __ldcs(base + i * 128 + t);

    // Per-warp gamma: 4 coalesced loads/lane over [b][chunk(2)][d] partials.
    // idx = lane + 32*i -> j = idx & 63 = lane (i even) or lane+32 (i odd).
    const float fwa = __ldg(fw + d * Dk + lane);
    const float fwb = __ldg(fw + d * Dk + lane + 32);
    const float* gp = g_partial + b * 128;
    float acc = 0.f;
    #pragma unroll
    for (int i = 0; i < 4; i++) {
        const float p = __ldcg(gp + lane + 32 * i);
        acc = fmaf(p, (i & 1) ? fwb : fwa, acc);
    }
    acc *= (1.0f / Kk);
    #pragma unroll
    for (int off = 16; off > 0; off >>= 1)
        acc += __shfl_xor_sync(0xffffffffu, acc, off);   // all lanes hold dot
    const float g = 1.f + 1.f / (1.f + __expf(-(acc + __ldg(fb + d))));

    #pragma unroll
    for (int i = 0; i < 8; i++) {
        float4 o;
        o.x = fmaxf(e[i].x * g, 0.f); o.y = fmaxf(e[i].y * g, 0.f);
        o.z = fmaxf(e[i].z * g, 0.f); o.w = fmaxf(e[i].w * g, 0.f);
        base[i * 128 + t] = o;
    }
}

extern "C" void kernel_launch(void* const* d_in, const int* in_sizes, int n_in,
                              void* d_out, int out_size)
{
    const float* X   = (const float*)d_in[0];  // (B,D,T,H,W)
    const float* cw  = (const float*)d_in[1];  // (K,D)
    const float* sc  = (const float*)d_in[2];  // (K,D)
    const float* fcw = (const float*)d_in[3];  // (D,D)
    const float* fcb = (const float*)d_in[4];  // (D,)
    float* out = (float*)d_out;

    k_encode<<<GRIDA, 256>>>(X, cw, sc, out);
    k_scale<<<GRIDC, 128>>>(fcw, fcb, out);
}